// round 17
// baseline (speedup 1.0000x reference)
#include <cuda_runtime.h>
#include <math.h>

#define BB 8
#define TT 200
#define UU 50
#define VV 1024

#define FRONT 64
#define RW    313                   // 64 front + 200 data + 49 back; stride 313=25 mod 32, conflict-free
#define NROWS (UU + (UU - 1) + 1)   // 50 blank + 49 emit + 1 dummy = 100
#define PADSZ (NROWS * RW)          // 31300 floats per batch
#define MITER 149                   // fused-2 iterations (R8 schedule)

#define INV_LN2 1.4426950408889634f
#define LN2     0.6931471805599453f
#define NEG_INF __int_as_float(0xff800000)
#define SENT    (-1.0e30f)

__device__ __forceinline__ float ex2f(float x) {
    float r; asm("ex2.approx.f32 %0, %1;" : "=f"(r) : "f"(x)); return r;
}
__device__ __forceinline__ float lg2f(float x) {
    float r; asm("lg2.approx.f32 %0, %1;" : "=f"(r) : "f"(x)); return r;
}

// Padded per-batch scratch, log2-domain normalized log-probs (R8 layout):
// rows 0..49 blank[u], rows 50..98 emit[u], row 99 dummy (all SENT).
__device__ float g_pad[BB * PADSZ];

// ---------------------------------------------------------------------------
// Phase 1: identical to the R8 kernel that passed at 23.0us.
// ---------------------------------------------------------------------------
__global__ void __launch_bounds__(64)
lse_gather_kernel(const float* __restrict__ h,
                  const int* __restrict__ targets,
                  float* __restrict__ out) {
    int bu = blockIdx.x;
    int b = bu / UU, u = bu % UU;
    int w = threadIdx.x >> 5, lane = threadIdx.x & 31;

    if (bu == 0 && threadIdx.x == 0) *out = 0.0f;

    float* batch = g_pad + b * PADSZ;

    if (w == 1 && u >= UU - 1) {
        float* dr = batch + (UU + UU - 1) * RW;     // dummy row
        for (int i = lane; i < RW; i += 32) dr[i] = SENT;
        return;
    }

    int v = (w == 1) ? targets[b * (UU - 1) + u] : 0;
    float* row = batch + ((w == 0) ? u : UU + u) * RW;

#pragma unroll
    for (int i = lane; i < FRONT; i += 32) row[i] = SENT;
#pragma unroll
    for (int i = FRONT + TT + lane; i < RW; i += 32) row[i] = SENT;
    if (w == 0 && u == 0 && lane == 0) row[FRONT - 1] = 0.0f;   // DP seed

    const float* base = h + (size_t)b * TT * UU * VV + (size_t)u * VV + v;

    float x[7];
#pragma unroll
    for (int i = 0; i < 7; ++i) {
        int t = lane + 32 * i;
        x[i] = (t < TT) ? base[(size_t)t * (UU * VV)] * INV_LN2 : NEG_INF;
    }

    float m = x[0];
#pragma unroll
    for (int i = 1; i < 7; ++i) m = fmaxf(m, x[i]);
#pragma unroll
    for (int o = 16; o > 0; o >>= 1) m = fmaxf(m, __shfl_xor_sync(0xffffffffu, m, o));

    float s = 0.0f;
#pragma unroll
    for (int i = 0; i < 7; ++i) s += ex2f(x[i] - m);
#pragma unroll
    for (int o = 16; o > 0; o >>= 1) s += __shfl_xor_sync(0xffffffffu, s, o);

    float lse = m + lg2f(s);

#pragma unroll
    for (int i = 0; i < 7; ++i) {
        int t = lane + 32 * i;
        if (t < TT) row[FRONT + t] = x[i] - lse;
    }
}

// ---------------------------------------------------------------------------
// Phase 2: R8 fused-2 wavefront, arithmetic in exact (m, S) pair form.
// alpha = m + lg2(S). Per cell: M = max(u, y) over m-proxies (args <= 0 by
// construction), S = fma(Sp, ex2(u-M), Sl*ex2(y-M)). No lg2 in the loop.
// Renorm every 4 iterations: exponent of S moved into m (exact, int ops).
// ---------------------------------------------------------------------------
__global__ void __launch_bounds__(256)
rnnt_dp_kernel(const int* __restrict__ input_lens,
               const int* __restrict__ target_lens,
               float* __restrict__ out) {
    extern __shared__ float sm[];
    float* sb    = sm;
    float* se    = sm + UU * RW;
    float* dummy = sm + (UU + UU - 1) * RW;

    int b = blockIdx.x;
    int tid = threadIdx.x;

    {   // flat stage, 16B
        const float4* src = (const float4*)(g_pad + b * PADSZ);
        float4* dst = (float4*)sm;
#pragma unroll 4
        for (int i = tid; i < PADSZ / 4; i += 256) dst[i] = src[i];
    }
    __syncthreads();
    if (tid >= 32) return;

    int ti = input_lens[b] - 1;     // >= 99
    int ui = target_lens[b] - 1;    // >= 24

    int k = tid;
    int jB = 32 + k;
    int srcLane = (k + 31) & 31;

    const float* pAb = sb + k * RW + (FRONT - 2 * k - 3);                                 // blank[k][t1-1],[t1]
    const float* pAe = ((k > 0) ? se + (k - 1) * RW : dummy) + (FRONT - 2 * k - 2);       // emit[k-1][t1],[t1+1]
    const float* pBb = ((jB < UU) ? sb + jB * RW       : dummy) + (FRONT - 2 * k - 67);   // blank[jB]
    const float* pBe = ((jB < UU) ? se + (jB - 1) * RW : dummy) + (FRONT - 2 * k - 66);   // emit[jB-1]

    bool tiOdd = (ti & 1) != 0;
    int mCapA = (k  == ui) ? (ti >> 1) + k + 1  : -1;
    int mCapB = (jB == ui) ? (ti >> 1) + k + 33 : -1;

    // carries (m, S): alpha of previous block's cell2
    float cmA = (k == 0) ? 0.0f : SENT, csA = 1.0f;
    float cmB = SENT, csB = 1.0f;
    // exports (cell1, cell2 pairs)
    float em1A = SENT, es1A = 1.0f, em2A = SENT, es2A = 1.0f;
    float em1B = SENT, es1B = 1.0f, em2B = SENT, es2B = 1.0f;
    float finM = 0.0f, finS = 1.0f;
    bool is31 = (k == 31);

    // prefetch m=1 operands
    float bA0 = pAb[2], bA1 = pAb[3], eA0 = pAe[2], eA1 = pAe[3];
    float bB0 = pBb[2], bB1 = pBb[3], eB0 = pBe[2], eB1 = pBe[3];

#pragma unroll 4
    for (int m = 1; m <= MITER; ++m) {
        float nm1A = __shfl_sync(0xffffffffu, em1A, srcLane);
        float ns1A = __shfl_sync(0xffffffffu, es1A, srcLane);
        float nm2A = __shfl_sync(0xffffffffu, em2A, srcLane);
        float ns2A = __shfl_sync(0xffffffffu, es2A, srcLane);
        float nm1B = __shfl_sync(0xffffffffu, em1B, srcLane);
        float ns1B = __shfl_sync(0xffffffffu, es1B, srcLane);
        float nm2B = __shfl_sync(0xffffffffu, em2B, srcLane);
        float ns2B = __shfl_sync(0xffffffffu, es2B, srcLane);

        float cbA0 = bA0, cbA1 = bA1, ceA0 = eA0, ceA1 = eA1;
        float cbB0 = bB0, cbB1 = bB1, ceB0 = eB0, ceB1 = eB1;
        bA0 = pAb[2 * m + 2]; bA1 = pAb[2 * m + 3];   // prefetch m+1 (off-chain)
        eA0 = pAe[2 * m + 2]; eA1 = pAe[2 * m + 3];
        bB0 = pBb[2 * m + 2]; bB1 = pBb[2 * m + 3];
        eB0 = pBe[2 * m + 2]; eB1 = pBe[2 * m + 3];

        // ---- slot A ----
        float uA  = cmA + cbA0;
        float yA  = nm1A + ceA0;
        float M1A = fmaxf(uA, yA);
        float S1A = fmaf(csA, ex2f(uA - M1A), ns1A * ex2f(yA - M1A));
        float u2A = M1A + cbA1;
        float y2A = nm2A + ceA1;
        float M2A = fmaxf(u2A, y2A);
        float S2A = fmaf(S1A, ex2f(u2A - M2A), ns2A * ex2f(y2A - M2A));

        // ---- slot B ----
        float uB  = cmB + cbB0;
        float yB  = nm1B + ceB0;
        float M1B = fmaxf(uB, yB);
        float S1B = fmaf(csB, ex2f(uB - M1B), ns1B * ex2f(yB - M1B));
        float u2B = M1B + cbB1;
        float y2B = nm2B + ceB1;
        float M2B = fmaxf(u2B, y2B);
        float S2B = fmaf(S1B, ex2f(u2B - M2B), ns2B * ex2f(y2B - M2B));

        if (m == mCapA) { finM = tiOdd ? M2A : M1A; finS = tiOdd ? S2A : S1A; }
        if (m == mCapB) { finM = tiOdd ? M2B : M1B; finS = tiOdd ? S2B : S1B; }

        // exports (pre-renorm; lane 31 mirrors A into the B channel)
        em1A = M1A; es1A = S1A; em2A = M2A; es2A = S2A;
        em1B = is31 ? M1A : M1B; es1B = is31 ? S1A : S1B;
        em2B = is31 ? M2A : M2B; es2B = is31 ? S2A : S2B;

        // carry + periodic exact renorm (S exponent -> m)
        if ((m & 3) == 0) {
            int biA = __float_as_int(S2A);
            int eA_ = (biA >> 23) - 127;
            S2A = __int_as_float(biA - (eA_ << 23));
            M2A = M2A + (float)eA_;
            int biB = __float_as_int(S2B);
            int eB_ = (biB >> 23) - 127;
            S2B = __int_as_float(biB - (eB_ << 23));
            M2B = M2B + (float)eB_;
        }
        cmA = M2A; csA = S2A;
        cmB = M2B; csB = S2B;
    }

    if (mCapA >= 0 || mCapB >= 0) {
        float loss2 = finM + lg2f(finS) + sb[ui * RW + FRONT + ti];
        atomicAdd(out, -loss2 * LN2 * (1.0f / BB));
    }
}

// ---------------------------------------------------------------------------
extern "C" void kernel_launch(void* const* d_in, const int* in_sizes, int n_in,
                              void* d_out, int out_size) {
    const float* h           = (const float*)d_in[0];
    const int*   targets     = (const int*)d_in[1];
    const int*   input_lens  = (const int*)d_in[2];
    const int*   target_lens = (const int*)d_in[3];
    float* out = (float*)d_out;

    // +256B slack: final (discarded) prefetch may read past the dummy row.
    size_t smem = (size_t)PADSZ * sizeof(float) + 256;
    cudaFuncSetAttribute(rnnt_dp_kernel,
                         cudaFuncAttributeMaxDynamicSharedMemorySize, (int)smem);

    lse_gather_kernel<<<BB * UU, 64>>>(h, targets, out);
    rnnt_dp_kernel<<<BB, 256, smem>>>(input_lens, target_lens, out);
}